// round 7
// baseline (speedup 1.0000x reference)
#include <cuda_runtime.h>
#include <cuda_bf16.h>
#include <cstdint>

#define N_NODES 50000
#define N_PAD   50176          // 196 * 256
#define R_REL   16
#define B_BASES 8
#define DIN     128
#define DOUT    128
#define NNZ     1600000
#define TILE_M  256
#define T_TILES 196            // ceil(50000/256)
#define CTAS_PER_B 18

typedef unsigned int uint;

// Scratch: device globals (no allocation allowed)
__device__ __nv_bfloat16 g_Xh[(size_t)N_PAD * DIN];
__device__ __nv_bfloat16 g_Xl[(size_t)N_PAD * DIN];
__device__ __nv_bfloat16 g_BTh[B_BASES * DOUT * DIN];
__device__ __nv_bfloat16 g_BTl[B_BASES * DOUT * DIN];
__device__ float g_XB[(size_t)B_BASES * N_NODES * DOUT];   // 204.8 MB
__device__ float g_FW[(size_t)R_REL * N_NODES * DOUT];     // 409.6 MB
__device__ int   g_idx64;
// CSR binning scratch
__device__ int   g_cnt[N_NODES];
__device__ int   g_start[N_NODES + 1];
__device__ int   g_cursor[N_NODES];
__device__ int2  g_edge[NNZ];

// ---------------------------------------------------------------------------
__device__ __forceinline__ uint32_t smem_u32(const void* p) {
    uint32_t a;
    asm("{ .reg .u64 t; cvta.to.shared.u64 t, %1; cvt.u32.u64 %0, t; }"
        : "=r"(a) : "l"(p));
    return a;
}
__device__ __forceinline__ void ldsm_x4(uint r[4], uint32_t addr) {
    asm volatile("ldmatrix.sync.aligned.m8n8.x4.shared.b16 {%0,%1,%2,%3}, [%4];"
                 : "=r"(r[0]), "=r"(r[1]), "=r"(r[2]), "=r"(r[3]) : "r"(addr));
}
__device__ __forceinline__ void mma_bf16(float c[4], const uint a[4], const uint b0, const uint b1) {
    asm volatile("mma.sync.aligned.m16n8k16.row.col.f32.bf16.bf16.f32 "
                 "{%0,%1,%2,%3},{%4,%5,%6,%7},{%8,%9},{%0,%1,%2,%3};"
                 : "+f"(c[0]), "+f"(c[1]), "+f"(c[2]), "+f"(c[3])
                 : "r"(a[0]), "r"(a[1]), "r"(a[2]), "r"(a[3]), "r"(b0), "r"(b1));
}

// ---------------------------------------------------------------------------
__global__ void detect_dtype_kernel(const unsigned int* __restrict__ rows_raw) {
    bool all_hi_zero = true;
    for (int i = 0; i < 64; i++)
        if (rows_raw[2 * i + 1] != 0u) { all_hi_zero = false; break; }
    g_idx64 = all_hi_zero ? 1 : 0;
}

__global__ void zero_cnt_kernel() {
    int i = blockIdx.x * blockDim.x + threadIdx.x;
    if (i < N_NODES) g_cnt[i] = 0;
}

__global__ void hist_kernel(const void* __restrict__ rows) {
    const int e = blockIdx.x * blockDim.x + threadIdx.x;
    if (e >= NNZ) return;
    int row = g_idx64 ? (int)((const unsigned int*)rows)[2 * e]
                      : ((const int*)rows)[e];
    atomicAdd(&g_cnt[row], 1);
}

__global__ void __launch_bounds__(1024, 1) scan_kernel() {
    __shared__ int wsum[32];
    __shared__ int carry;
    const int tid = threadIdx.x, lane = tid & 31, wid = tid >> 5;
    if (tid == 0) carry = 0;
    __syncthreads();
    for (int base = 0; base < N_NODES; base += 1024) {
        const int i = base + tid;
        int v = (i < N_NODES) ? g_cnt[i] : 0;
        int x = v;
#pragma unroll
        for (int off = 1; off < 32; off <<= 1) {
            int y = __shfl_up_sync(0xffffffffu, x, off);
            if (lane >= off) x += y;
        }
        if (lane == 31) wsum[wid] = x;
        __syncthreads();
        if (wid == 0) {
            int s = wsum[lane];
#pragma unroll
            for (int off = 1; off < 32; off <<= 1) {
                int y = __shfl_up_sync(0xffffffffu, s, off);
                if (lane >= off) s += y;
            }
            wsum[lane] = s;
        }
        __syncthreads();
        const int warpOff = (wid == 0) ? 0 : wsum[wid - 1];
        const int excl = carry + warpOff + x - v;
        if (i < N_NODES) { g_start[i] = excl; g_cursor[i] = excl; }
        __syncthreads();
        if (tid == 0) carry += wsum[31];
        __syncthreads();
    }
    if (tid == 0) g_start[N_NODES] = carry;
}

__global__ void fill_kernel(const void* __restrict__ rows,
                            const void* __restrict__ cols,
                            const float* __restrict__ vals) {
    const int e = blockIdx.x * blockDim.x + threadIdx.x;
    if (e >= NNZ) return;
    int row, col;
    if (g_idx64) {
        row = (int)((const unsigned int*)rows)[2 * e];
        col = (int)((const unsigned int*)cols)[2 * e];
    } else {
        row = ((const int*)rows)[e];
        col = ((const int*)cols)[e];
    }
    const int pos = atomicAdd(&g_cursor[row], 1);
    g_edge[pos] = make_int2(col, __float_as_int(vals[e]));
}

// ---------------------------------------------------------------------------
__global__ void prep_x_kernel(const float* __restrict__ X) {
    const int id = blockIdx.x * blockDim.x + threadIdx.x;
    if (id >= (N_PAD * DIN) / 8) return;
    const size_t base = (size_t)id * 8;
    const int row = (int)(base >> 7);
    __nv_bfloat16 h[8], l[8];
    if (row < N_NODES) {
        float v[8];
        *(float4*)&v[0] = *(const float4*)(X + base);
        *(float4*)&v[4] = *(const float4*)(X + base + 4);
#pragma unroll
        for (int i = 0; i < 8; i++) {
            h[i] = __float2bfloat16_rn(v[i]);
            l[i] = __float2bfloat16_rn(v[i] - __bfloat162float(h[i]));
        }
    } else {
#pragma unroll
        for (int i = 0; i < 8; i++) { h[i] = __float2bfloat16_rn(0.f); l[i] = h[i]; }
    }
    *(uint4*)(g_Xh + base) = *(uint4*)h;
    *(uint4*)(g_Xl + base) = *(uint4*)l;
}

__global__ void prep_bt_kernel(const float* __restrict__ basis) {
    const int id = blockIdx.x * blockDim.x + threadIdx.x;
    if (id >= B_BASES * DOUT * (DIN / 4)) return;
    const int k4 = (id & 31) * 4;
    const int n  = (id >> 5) & 127;
    const int b  = id >> 12;
    __nv_bfloat16 h[4], l[4];
#pragma unroll
    for (int i = 0; i < 4; i++) {
        float v = basis[(size_t)b * DIN * DOUT + (size_t)(k4 + i) * DOUT + n];
        h[i] = __float2bfloat16_rn(v);
        l[i] = __float2bfloat16_rn(v - __bfloat162float(h[i]));
    }
    const size_t off = (size_t)b * DOUT * DIN + (size_t)n * DIN + k4;
    *(uint2*)(g_BTh + off) = *(uint2*)h;
    *(uint2*)(g_BTl + off) = *(uint2*)l;
}

// ---------------------------------------------------------------------------
// XB[b] = X @ basis[b] via mma.sync bf16 split-3.
// Persistent-B: grid (18, 8); CTA pins Bh/Bl (64 KB) and loops 256-row X
// tiles (Xh/Xl full-K, 128 KB). 8 warps, warp tile 64x64 (2m x 2n grid of
// warps over the 256x128 CTA tile -> wm in 0..3 across 256 rows).
// Row stride 256 B (128 bf16); 16B-chunk XOR swizzle (c ^ (row&7)).
// ---------------------------------------------------------------------------
#define S_BH 0
#define S_BL 32768
#define S_XH 65536
#define S_XL 131072
#define S_TOTAL 196608

__global__ void __launch_bounds__(256, 1)
gemm_mma_kernel(int dummy) {
    extern __shared__ __align__(1024) unsigned char smem[];
    const uint32_t sbase = smem_u32(smem);
    const int tid  = threadIdx.x;
    const int wid  = tid >> 5;
    const int lane = tid & 31;
    const int b    = blockIdx.y;

    const int wm = wid >> 1;          // 0..3 (64 rows each over 256)
    const int wn = wid & 1;           // 0..1 (64 cols each)

    // --- load B tiles once (2048 chunks per array, 8 per thread) ---
    {
        const size_t bBase = (size_t)b * DOUT * DIN;
#pragma unroll
        for (int i = 0; i < 8; i++) {
            const int slot = tid * 8 + i;          // 0..2047
            const int row  = slot >> 4;            // 0..127
            const int c    = slot & 15;            // 16B chunk
            const uint32_t dst = (uint32_t)(row * 256 + ((c ^ (row & 7)) << 4));
            const size_t src = bBase + (size_t)row * DIN + c * 8;
            *(uint4*)(smem + S_BH + dst) = *(const uint4*)(g_BTh + src);
            *(uint4*)(smem + S_BL + dst) = *(const uint4*)(g_BTl + src);
        }
    }

    // ldmatrix lane components
    const int a_row0 = wm * 64 + (lane & 15);
    const int a_ch   = lane >> 4;
    const int b_row0 = wn * 64 + (lane & 7) + ((lane >> 4) << 3);
    const int b_ch   = (lane >> 3) & 1;

    const int g  = lane >> 2;
    const int t2 = (lane & 3) * 2;
    float* const outBase = g_XB + (size_t)b * N_NODES * DOUT;

    for (int t = blockIdx.x; t < T_TILES; t += CTAS_PER_B) {
        const int m0 = t * TILE_M;

        // --- load X tile (4096 chunks per array, 16 per thread) ---
#pragma unroll
        for (int i = 0; i < 16; i++) {
            const int slot = tid * 16 + i;         // 0..4095
            const int row  = slot >> 4;            // 0..255 (row == tid here)
            const int c    = slot & 15;
            const uint32_t dst = (uint32_t)(row * 256 + ((c ^ (row & 7)) << 4));
            const size_t src = (size_t)(m0 + row) * DIN + c * 8;
            *(uint4*)(smem + S_XH + dst) = *(const uint4*)(g_Xh + src);
            *(uint4*)(smem + S_XL + dst) = *(const uint4*)(g_Xl + src);
        }
        __syncthreads();

        float acc[4][8][4];
#pragma unroll
        for (int mf = 0; mf < 4; mf++)
#pragma unroll
            for (int nf = 0; nf < 8; nf++)
#pragma unroll
                for (int q = 0; q < 4; q++) acc[mf][nf][q] = 0.f;

#pragma unroll
        for (int kf = 0; kf < 8; kf++) {
            uint Ah[4][4], Al[4][4];
#pragma unroll
            for (int mf = 0; mf < 4; mf++) {
                const int row = a_row0 + mf * 16;
                const uint32_t addr = (uint32_t)(row * 256 +
                    (((kf * 2 + a_ch) ^ (row & 7)) << 4));
                ldsm_x4(Ah[mf], sbase + S_XH + addr);
                ldsm_x4(Al[mf], sbase + S_XL + addr);
            }
#pragma unroll
            for (int p = 0; p < 4; p++) {
                const int row = b_row0 + p * 16;
                const uint32_t addr = (uint32_t)(row * 256 +
                    (((kf * 2 + b_ch) ^ (row & 7)) << 4));
                uint Bh[4];
                ldsm_x4(Bh, sbase + S_BH + addr);
#pragma unroll
                for (int mf = 0; mf < 4; mf++) {
                    mma_bf16(acc[mf][2 * p],     Ah[mf], Bh[0], Bh[1]);
                    mma_bf16(acc[mf][2 * p + 1], Ah[mf], Bh[2], Bh[3]);
                    mma_bf16(acc[mf][2 * p],     Al[mf], Bh[0], Bh[1]);
                    mma_bf16(acc[mf][2 * p + 1], Al[mf], Bh[2], Bh[3]);
                }
                uint Bl[4];
                ldsm_x4(Bl, sbase + S_BL + addr);
#pragma unroll
                for (int mf = 0; mf < 4; mf++) {
                    mma_bf16(acc[mf][2 * p],     Ah[mf], Bl[0], Bl[1]);
                    mma_bf16(acc[mf][2 * p + 1], Ah[mf], Bl[2], Bl[3]);
                }
            }
        }
        __syncthreads();   // all warps done with smem X before next tile load

        // --- epilogue: write XB[b] fp32 ---
#pragma unroll
        for (int mf = 0; mf < 4; mf++) {
            const int r0 = m0 + wm * 64 + mf * 16 + g;
#pragma unroll
            for (int nf = 0; nf < 8; nf++) {
                const int col = wn * 64 + nf * 8 + t2;
                if (r0 < N_NODES)
                    *(float2*)(outBase + (size_t)r0 * DOUT + col) =
                        make_float2(acc[mf][nf][0], acc[mf][nf][1]);
                if (r0 + 8 < N_NODES)
                    *(float2*)(outBase + (size_t)(r0 + 8) * DOUT + col) =
                        make_float2(acc[mf][nf][2], acc[mf][nf][3]);
            }
        }
    }
}

// ---------------------------------------------------------------------------
// FW[r][n][d] = sum_b comp[r][b] * XB[b][n][d]
// ---------------------------------------------------------------------------
__global__ __launch_bounds__(256)
void combine_kernel(const float* __restrict__ comp) {
    __shared__ float cs[R_REL * B_BASES];
    if (threadIdx.x < R_REL * B_BASES) cs[threadIdx.x] = comp[threadIdx.x];
    __syncthreads();

    const int id = blockIdx.x * blockDim.x + threadIdx.x;
    if (id >= N_NODES * 32) return;
    const int n  = id >> 5;
    const int d4 = (id & 31) * 4;

    float4 xb[8];
#pragma unroll
    for (int b = 0; b < B_BASES; b++)
        xb[b] = __ldg((const float4*)(g_XB + ((size_t)b * N_NODES + n) * DOUT + d4));

#pragma unroll
    for (int r = 0; r < R_REL; r++) {
        float4 o = make_float4(0.f, 0.f, 0.f, 0.f);
#pragma unroll
        for (int b = 0; b < B_BASES; b++) {
            const float c = cs[r * B_BASES + b];
            o.x += c * xb[b].x;
            o.y += c * xb[b].y;
            o.z += c * xb[b].z;
            o.w += c * xb[b].w;
        }
        *(float4*)(g_FW + ((size_t)r * N_NODES + n) * DOUT + d4) = o;
    }
}

// ---------------------------------------------------------------------------
// Sorted scatter: one warp per output row; register accumulation; single
// non-atomic row write.
// ---------------------------------------------------------------------------
__global__ void __launch_bounds__(256)
scatter2_kernel(float* __restrict__ out) {
    const int warpId = (blockIdx.x * blockDim.x + threadIdx.x) >> 5;
    if (warpId >= N_NODES) return;
    const int lane = threadIdx.x & 31;

    const int s = g_start[warpId];
    const int e = g_start[warpId + 1];

    float4 acc = make_float4(0.f, 0.f, 0.f, 0.f);
    int i = s;
    for (; i + 4 <= e; i += 4) {
        int2 e0 = g_edge[i], e1 = g_edge[i + 1], e2 = g_edge[i + 2], e3 = g_edge[i + 3];
        float4 f0 = __ldg((const float4*)(g_FW + (size_t)e0.x * DOUT) + lane);
        float4 f1 = __ldg((const float4*)(g_FW + (size_t)e1.x * DOUT) + lane);
        float4 f2 = __ldg((const float4*)(g_FW + (size_t)e2.x * DOUT) + lane);
        float4 f3 = __ldg((const float4*)(g_FW + (size_t)e3.x * DOUT) + lane);
        const float v0 = __int_as_float(e0.y), v1 = __int_as_float(e1.y);
        const float v2 = __int_as_float(e2.y), v3 = __int_as_float(e3.y);
        acc.x += v0 * f0.x + v1 * f1.x + v2 * f2.x + v3 * f3.x;
        acc.y += v0 * f0.y + v1 * f1.y + v2 * f2.y + v3 * f3.y;
        acc.z += v0 * f0.z + v1 * f1.z + v2 * f2.z + v3 * f3.z;
        acc.w += v0 * f0.w + v1 * f1.w + v2 * f2.w + v3 * f3.w;
    }
    for (; i < e; i++) {
        int2 ed = g_edge[i];
        float4 f = __ldg((const float4*)(g_FW + (size_t)ed.x * DOUT) + lane);
        const float v = __int_as_float(ed.y);
        acc.x += v * f.x; acc.y += v * f.y; acc.z += v * f.z; acc.w += v * f.w;
    }
    *(float4*)(out + (size_t)warpId * DOUT + lane * 4) = acc;
}

// ---------------------------------------------------------------------------
extern "C" void kernel_launch(void* const* d_in, const int* in_sizes, int n_in,
                              void* d_out, int out_size) {
    const float* X      = (const float*)d_in[0];
    const void*  A_rows = d_in[1];
    const void*  A_cols = d_in[2];
    const float* A_vals = (const float*)d_in[3];
    const float* basis  = (const float*)d_in[4];
    const float* comp   = (const float*)d_in[5];
    float* out = (float*)d_out;

    cudaFuncSetAttribute(gemm_mma_kernel,
                         cudaFuncAttributeMaxDynamicSharedMemorySize, S_TOTAL);

    // gemm_mma_kernel stays launch #4 so ncu (-s 5 -c 1) profiles it.
    detect_dtype_kernel<<<1, 1>>>((const unsigned int*)A_rows);         // 1

    const int px = (N_PAD * DIN) / 8;
    prep_x_kernel<<<(px + 255) / 256, 256>>>(X);                        // 2
    const int pb = B_BASES * DOUT * (DIN / 4);
    prep_bt_kernel<<<(pb + 255) / 256, 256>>>(basis);                   // 3

    dim3 ggrid(CTAS_PER_B, B_BASES);
    gemm_mma_kernel<<<ggrid, 256, S_TOTAL>>>(0);                        // 4 (profiled)

    zero_cnt_kernel<<<(N_NODES + 255) / 256, 256>>>();                  // 5
    hist_kernel<<<(NNZ + 255) / 256, 256>>>(A_rows);                    // 6
    scan_kernel<<<1, 1024>>>();                                         // 7
    fill_kernel<<<(NNZ + 255) / 256, 256>>>(A_rows, A_cols, A_vals);    // 8

    const int cthreads = N_NODES * 32;
    combine_kernel<<<(cthreads + 255) / 256, 256>>>(comp);              // 9

    const long long sthreads = (long long)N_NODES * 32;
    scatter2_kernel<<<(unsigned)((sthreads + 255) / 256), 256>>>(out);  // 10
}

// round 8
// speedup vs baseline: 1.1674x; 1.1674x over previous
#include <cuda_runtime.h>
#include <cuda_bf16.h>
#include <cstdint>

#define N_NODES 50000
#define N_PAD   50048          // 391 * 128
#define R_REL   16
#define B_BASES 8
#define DIN     128
#define DOUT    128
#define NNZ     1600000
#define M_TILES 391

typedef unsigned int uint;

// Scratch: device globals (no allocation allowed)
__device__ __nv_bfloat16 g_Xh[(size_t)N_PAD * DIN];
__device__ __nv_bfloat16 g_Xl[(size_t)N_PAD * DIN];
__device__ __nv_bfloat16 g_BTh[B_BASES * DOUT * DIN];
__device__ __nv_bfloat16 g_BTl[B_BASES * DOUT * DIN];
__device__ float g_XB[(size_t)B_BASES * N_NODES * DOUT];   // 204.8 MB
__device__ float g_FW[(size_t)R_REL * N_NODES * DOUT];     // 409.6 MB
__device__ int   g_idx64;
// CSR binning scratch
__device__ int   g_cnt[N_NODES];
__device__ int   g_start[N_NODES + 1];
__device__ int   g_cursor[N_NODES];
__device__ int2  g_edge[NNZ];

// ---------------------------------------------------------------------------
__device__ __forceinline__ uint32_t smem_u32(const void* p) {
    uint32_t a;
    asm("{ .reg .u64 t; cvta.to.shared.u64 t, %1; cvt.u32.u64 %0, t; }"
        : "=r"(a) : "l"(p));
    return a;
}
__device__ __forceinline__ void ldsm_x4(uint r[4], uint32_t addr) {
    asm volatile("ldmatrix.sync.aligned.m8n8.x4.shared.b16 {%0,%1,%2,%3}, [%4];"
                 : "=r"(r[0]), "=r"(r[1]), "=r"(r[2]), "=r"(r[3]) : "r"(addr));
}
__device__ __forceinline__ void mma_bf16(float c[4], const uint a[4], const uint b0, const uint b1) {
    asm volatile("mma.sync.aligned.m16n8k16.row.col.f32.bf16.bf16.f32 "
                 "{%0,%1,%2,%3},{%4,%5,%6,%7},{%8,%9},{%0,%1,%2,%3};"
                 : "+f"(c[0]), "+f"(c[1]), "+f"(c[2]), "+f"(c[3])
                 : "r"(a[0]), "r"(a[1]), "r"(a[2]), "r"(a[3]), "r"(b0), "r"(b1));
}
__device__ __forceinline__ void cp_async16(uint32_t dst, const void* src) {
    asm volatile("cp.async.cg.shared.global [%0], [%1], 16;" :: "r"(dst), "l"(src));
}
#define CP_COMMIT() asm volatile("cp.async.commit_group;" ::: "memory")
#define CP_WAIT(n)  asm volatile("cp.async.wait_group %0;" :: "n"(n) : "memory")

// ---------------------------------------------------------------------------
__global__ void detect_dtype_kernel(const unsigned int* __restrict__ rows_raw) {
    bool all_hi_zero = true;
    for (int i = 0; i < 64; i++)
        if (rows_raw[2 * i + 1] != 0u) { all_hi_zero = false; break; }
    g_idx64 = all_hi_zero ? 1 : 0;
}

__global__ void zero_cnt_kernel() {
    int i = blockIdx.x * blockDim.x + threadIdx.x;
    if (i < N_NODES) g_cnt[i] = 0;
}

__global__ void hist_kernel(const void* __restrict__ rows) {
    const int e = blockIdx.x * blockDim.x + threadIdx.x;
    if (e >= NNZ) return;
    int row = g_idx64 ? (int)((const unsigned int*)rows)[2 * e]
                      : ((const int*)rows)[e];
    atomicAdd(&g_cnt[row], 1);
}

__global__ void __launch_bounds__(1024, 1) scan_kernel() {
    __shared__ int wsum[32];
    __shared__ int carry;
    const int tid = threadIdx.x, lane = tid & 31, wid = tid >> 5;
    if (tid == 0) carry = 0;
    __syncthreads();
    for (int base = 0; base < N_NODES; base += 1024) {
        const int i = base + tid;
        int v = (i < N_NODES) ? g_cnt[i] : 0;
        int x = v;
#pragma unroll
        for (int off = 1; off < 32; off <<= 1) {
            int y = __shfl_up_sync(0xffffffffu, x, off);
            if (lane >= off) x += y;
        }
        if (lane == 31) wsum[wid] = x;
        __syncthreads();
        if (wid == 0) {
            int s = wsum[lane];
#pragma unroll
            for (int off = 1; off < 32; off <<= 1) {
                int y = __shfl_up_sync(0xffffffffu, s, off);
                if (lane >= off) s += y;
            }
            wsum[lane] = s;
        }
        __syncthreads();
        const int warpOff = (wid == 0) ? 0 : wsum[wid - 1];
        const int excl = carry + warpOff + x - v;
        if (i < N_NODES) { g_start[i] = excl; g_cursor[i] = excl; }
        __syncthreads();
        if (tid == 0) carry += wsum[31];
        __syncthreads();
    }
    if (tid == 0) g_start[N_NODES] = carry;
}

__global__ void fill_kernel(const void* __restrict__ rows,
                            const void* __restrict__ cols,
                            const float* __restrict__ vals) {
    const int e = blockIdx.x * blockDim.x + threadIdx.x;
    if (e >= NNZ) return;
    int row, col;
    if (g_idx64) {
        row = (int)((const unsigned int*)rows)[2 * e];
        col = (int)((const unsigned int*)cols)[2 * e];
    } else {
        row = ((const int*)rows)[e];
        col = ((const int*)cols)[e];
    }
    const int pos = atomicAdd(&g_cursor[row], 1);
    g_edge[pos] = make_int2(col, __float_as_int(vals[e]));
}

// ---------------------------------------------------------------------------
__global__ void prep_x_kernel(const float* __restrict__ X) {
    const int id = blockIdx.x * blockDim.x + threadIdx.x;
    if (id >= (N_PAD * DIN) / 8) return;
    const size_t base = (size_t)id * 8;
    const int row = (int)(base >> 7);
    __nv_bfloat16 h[8], l[8];
    if (row < N_NODES) {
        float v[8];
        *(float4*)&v[0] = *(const float4*)(X + base);
        *(float4*)&v[4] = *(const float4*)(X + base + 4);
#pragma unroll
        for (int i = 0; i < 8; i++) {
            h[i] = __float2bfloat16_rn(v[i]);
            l[i] = __float2bfloat16_rn(v[i] - __bfloat162float(h[i]));
        }
    } else {
#pragma unroll
        for (int i = 0; i < 8; i++) { h[i] = __float2bfloat16_rn(0.f); l[i] = h[i]; }
    }
    *(uint4*)(g_Xh + base) = *(uint4*)h;
    *(uint4*)(g_Xl + base) = *(uint4*)l;
}

__global__ void prep_bt_kernel(const float* __restrict__ basis) {
    const int id = blockIdx.x * blockDim.x + threadIdx.x;
    if (id >= B_BASES * DOUT * (DIN / 4)) return;
    const int k4 = (id & 31) * 4;
    const int n  = (id >> 5) & 127;
    const int b  = id >> 12;
    __nv_bfloat16 h[4], l[4];
#pragma unroll
    for (int i = 0; i < 4; i++) {
        float v = basis[(size_t)b * DIN * DOUT + (size_t)(k4 + i) * DOUT + n];
        h[i] = __float2bfloat16_rn(v);
        l[i] = __float2bfloat16_rn(v - __bfloat162float(h[i]));
    }
    const size_t off = (size_t)b * DOUT * DIN + (size_t)n * DIN + k4;
    *(uint2*)(g_BTh + off) = *(uint2*)h;
    *(uint2*)(g_BTl + off) = *(uint2*)l;
}

// ---------------------------------------------------------------------------
// XB[b] = X @ basis[b] via mma.sync bf16 split-3, cp.async double-buffered.
// grid (391, 8), 256 threads, 2 CTAs/SM (96 KB smem).
// B hi/lo full-K resident (64 KB, 256B rows, swizzle c^(row&7)).
// X in 4 k-chunks of 32, double buffered (2 x 16 KB, 64B rows,
// swizzle c^((row>>1)&3)).
// ---------------------------------------------------------------------------
#define S_BH   0
#define S_BL   32768
#define S_X    65536
#define XBUF   16384           // per X buffer: Xh 8KB @ +0, Xl 8KB @ +8192
#define S_TOTAL 98304

__global__ void __launch_bounds__(256, 2)
gemm_mma_kernel(int dummy) {
    extern __shared__ __align__(1024) unsigned char smem[];
    const uint32_t sbase = smem_u32(smem);
    const int tid  = threadIdx.x;
    const int wid  = tid >> 5;
    const int lane = tid & 31;
    const int b    = blockIdx.y;
    const int m0   = blockIdx.x * 128;

    const int wm = wid >> 1;          // 0..3 (32 rows)
    const int wn = wid & 1;           // 0..1 (64 cols)

    // --- prologue: async-load B (full K) then X chunk 0 ---
    {
        const size_t bBase = (size_t)b * DOUT * DIN;
#pragma unroll
        for (int i = 0; i < 8; i++) {
            const int slot = i * 256 + tid;        // 0..2047
            const int row  = slot >> 4;            // 0..127
            const int c    = slot & 15;
            const uint32_t dst = (uint32_t)(row * 256 + ((c ^ (row & 7)) << 4));
            const size_t src = bBase + (size_t)row * DIN + c * 8;
            cp_async16(sbase + S_BH + dst, g_BTh + src);
            cp_async16(sbase + S_BL + dst, g_BTl + src);
        }
    }
    CP_COMMIT();
#pragma unroll
    for (int i = 0; i < 2; i++) {
        const int slot = i * 256 + tid;            // 0..511
        const int row  = slot >> 2;                // 0..127
        const int c    = slot & 3;
        const uint32_t dst = (uint32_t)(row * 64 + ((c ^ ((row >> 1) & 3)) << 4));
        const size_t src = (size_t)(m0 + row) * DIN + c * 8;
        cp_async16(sbase + S_X + dst, g_Xh + src);
        cp_async16(sbase + S_X + 8192 + dst, g_Xl + src);
    }
    CP_COMMIT();

    float acc[2][8][4];
#pragma unroll
    for (int mf = 0; mf < 2; mf++)
#pragma unroll
        for (int nf = 0; nf < 8; nf++)
#pragma unroll
            for (int q = 0; q < 4; q++) acc[mf][nf][q] = 0.f;

    const int a_row0 = wm * 32 + (lane & 15);
    const int a_ch   = lane >> 4;
    const int b_row0 = wn * 64 + (lane & 7) + ((lane >> 4) << 3);
    const int b_ch   = (lane >> 3) & 1;

#pragma unroll
    for (int kc = 0; kc < 4; kc++) {
        // issue next chunk's loads before waiting on this one
        if (kc < 3) {
            const uint32_t xb = sbase + S_X + ((kc + 1) & 1) * XBUF;
#pragma unroll
            for (int i = 0; i < 2; i++) {
                const int slot = i * 256 + tid;
                const int row  = slot >> 2;
                const int c    = slot & 3;
                const uint32_t dst = (uint32_t)(row * 64 + ((c ^ ((row >> 1) & 3)) << 4));
                const size_t src = (size_t)(m0 + row) * DIN + (kc + 1) * 32 + c * 8;
                cp_async16(xb + dst, g_Xh + src);
                cp_async16(xb + 8192 + dst, g_Xl + src);
            }
            CP_COMMIT();
            CP_WAIT(1);
        } else {
            CP_WAIT(0);
        }
        __syncthreads();

        const uint32_t xh = sbase + S_X + (kc & 1) * XBUF;
        const uint32_t xl = xh + 8192;

#pragma unroll
        for (int kfi = 0; kfi < 2; kfi++) {
            const int kf = kc * 2 + kfi;           // global k16 index
            uint Ah[2][4], Al[2][4];
#pragma unroll
            for (int mf = 0; mf < 2; mf++) {
                const int row = a_row0 + mf * 16;
                const uint32_t addr = (uint32_t)(row * 64 +
                    (((kfi * 2 + a_ch) ^ ((row >> 1) & 3)) << 4));
                ldsm_x4(Ah[mf], xh + addr);
                ldsm_x4(Al[mf], xl + addr);
            }
#pragma unroll
            for (int p = 0; p < 4; p++) {
                const int row = b_row0 + p * 16;
                const uint32_t addr = (uint32_t)(row * 256 +
                    (((kf * 2 + b_ch) ^ (row & 7)) << 4));
                uint Bh[4];
                ldsm_x4(Bh, sbase + S_BH + addr);
#pragma unroll
                for (int mf = 0; mf < 2; mf++) {
                    mma_bf16(acc[mf][2 * p],     Ah[mf], Bh[0], Bh[1]);
                    mma_bf16(acc[mf][2 * p + 1], Ah[mf], Bh[2], Bh[3]);
                    mma_bf16(acc[mf][2 * p],     Al[mf], Bh[0], Bh[1]);
                    mma_bf16(acc[mf][2 * p + 1], Al[mf], Bh[2], Bh[3]);
                }
                uint Bl[4];
                ldsm_x4(Bl, sbase + S_BL + addr);
#pragma unroll
                for (int mf = 0; mf < 2; mf++) {
                    mma_bf16(acc[mf][2 * p],     Ah[mf], Bl[0], Bl[1]);
                    mma_bf16(acc[mf][2 * p + 1], Ah[mf], Bl[2], Bl[3]);
                }
            }
        }
        __syncthreads();   // done reading this buffer before it is refilled
    }

    // --- epilogue: write XB[b] fp32 ---
    float* outBase = g_XB + (size_t)b * N_NODES * DOUT;
    const int g = lane >> 2;
    const int t2 = (lane & 3) * 2;
#pragma unroll
    for (int mf = 0; mf < 2; mf++) {
        const int r0 = m0 + wm * 32 + mf * 16 + g;
#pragma unroll
        for (int nf = 0; nf < 8; nf++) {
            const int col = wn * 64 + nf * 8 + t2;
            if (r0 < N_NODES)
                *(float2*)(outBase + (size_t)r0 * DOUT + col) =
                    make_float2(acc[mf][nf][0], acc[mf][nf][1]);
            if (r0 + 8 < N_NODES)
                *(float2*)(outBase + (size_t)(r0 + 8) * DOUT + col) =
                    make_float2(acc[mf][nf][2], acc[mf][nf][3]);
        }
    }
}

// ---------------------------------------------------------------------------
// FW[r][n][d] = sum_b comp[r][b] * XB[b][n][d]
// ---------------------------------------------------------------------------
__global__ __launch_bounds__(256)
void combine_kernel(const float* __restrict__ comp) {
    __shared__ float cs[R_REL * B_BASES];
    if (threadIdx.x < R_REL * B_BASES) cs[threadIdx.x] = comp[threadIdx.x];
    __syncthreads();

    const int id = blockIdx.x * blockDim.x + threadIdx.x;
    if (id >= N_NODES * 32) return;
    const int n  = id >> 5;
    const int d4 = (id & 31) * 4;

    float4 xb[8];
#pragma unroll
    for (int b = 0; b < B_BASES; b++)
        xb[b] = __ldg((const float4*)(g_XB + ((size_t)b * N_NODES + n) * DOUT + d4));

#pragma unroll
    for (int r = 0; r < R_REL; r++) {
        float4 o = make_float4(0.f, 0.f, 0.f, 0.f);
#pragma unroll
        for (int b = 0; b < B_BASES; b++) {
            const float c = cs[r * B_BASES + b];
            o.x += c * xb[b].x;
            o.y += c * xb[b].y;
            o.z += c * xb[b].z;
            o.w += c * xb[b].w;
        }
        *(float4*)(g_FW + ((size_t)r * N_NODES + n) * DOUT + d4) = o;
    }
}

// ---------------------------------------------------------------------------
// Sorted scatter: one warp per output row; register accumulation; single
// non-atomic row write.
// ---------------------------------------------------------------------------
__global__ void __launch_bounds__(256)
scatter2_kernel(float* __restrict__ out) {
    const int warpId = (blockIdx.x * blockDim.x + threadIdx.x) >> 5;
    if (warpId >= N_NODES) return;
    const int lane = threadIdx.x & 31;

    const int s = g_start[warpId];
    const int e = g_start[warpId + 1];

    float4 acc = make_float4(0.f, 0.f, 0.f, 0.f);
    int i = s;
    for (; i + 4 <= e; i += 4) {
        int2 e0 = g_edge[i], e1 = g_edge[i + 1], e2 = g_edge[i + 2], e3 = g_edge[i + 3];
        float4 f0 = __ldg((const float4*)(g_FW + (size_t)e0.x * DOUT) + lane);
        float4 f1 = __ldg((const float4*)(g_FW + (size_t)e1.x * DOUT) + lane);
        float4 f2 = __ldg((const float4*)(g_FW + (size_t)e2.x * DOUT) + lane);
        float4 f3 = __ldg((const float4*)(g_FW + (size_t)e3.x * DOUT) + lane);
        const float v0 = __int_as_float(e0.y), v1 = __int_as_float(e1.y);
        const float v2 = __int_as_float(e2.y), v3 = __int_as_float(e3.y);
        acc.x += v0 * f0.x + v1 * f1.x + v2 * f2.x + v3 * f3.x;
        acc.y += v0 * f0.y + v1 * f1.y + v2 * f2.y + v3 * f3.y;
        acc.z += v0 * f0.z + v1 * f1.z + v2 * f2.z + v3 * f3.z;
        acc.w += v0 * f0.w + v1 * f1.w + v2 * f2.w + v3 * f3.w;
    }
    for (; i < e; i++) {
        int2 ed = g_edge[i];
        float4 f = __ldg((const float4*)(g_FW + (size_t)ed.x * DOUT) + lane);
        const float v = __int_as_float(ed.y);
        acc.x += v * f.x; acc.y += v * f.y; acc.z += v * f.z; acc.w += v * f.w;
    }
    *(float4*)(out + (size_t)warpId * DOUT + lane * 4) = acc;
}

// ---------------------------------------------------------------------------
extern "C" void kernel_launch(void* const* d_in, const int* in_sizes, int n_in,
                              void* d_out, int out_size) {
    const float* X      = (const float*)d_in[0];
    const void*  A_rows = d_in[1];
    const void*  A_cols = d_in[2];
    const float* A_vals = (const float*)d_in[3];
    const float* basis  = (const float*)d_in[4];
    const float* comp   = (const float*)d_in[5];
    float* out = (float*)d_out;

    cudaFuncSetAttribute(gemm_mma_kernel,
                         cudaFuncAttributeMaxDynamicSharedMemorySize, S_TOTAL);

    // gemm_mma_kernel stays launch #4 so ncu (-s 5 -c 1) profiles it.
    detect_dtype_kernel<<<1, 1>>>((const unsigned int*)A_rows);         // 1

    const int px = (N_PAD * DIN) / 8;
    prep_x_kernel<<<(px + 255) / 256, 256>>>(X);                        // 2
    const int pb = B_BASES * DOUT * (DIN / 4);
    prep_bt_kernel<<<(pb + 255) / 256, 256>>>(basis);                   // 3

    dim3 ggrid(M_TILES, B_BASES);
    gemm_mma_kernel<<<ggrid, 256, S_TOTAL>>>(0);                        // 4 (profiled)

    zero_cnt_kernel<<<(N_NODES + 255) / 256, 256>>>();                  // 5
    hist_kernel<<<(NNZ + 255) / 256, 256>>>(A_rows);                    // 6
    scan_kernel<<<1, 1024>>>();                                         // 7
    fill_kernel<<<(NNZ + 255) / 256, 256>>>(A_rows, A_cols, A_vals);    // 8

    const int cthreads = N_NODES * 32;
    combine_kernel<<<(cthreads + 255) / 256, 256>>>(comp);              // 9

    const long long sthreads = (long long)N_NODES * 32;
    scatter2_kernel<<<(unsigned)((sthreads + 255) / 256), 256>>>(out);  // 10
}

// round 9
// speedup vs baseline: 1.5009x; 1.2857x over previous
#include <cuda_runtime.h>
#include <cuda_bf16.h>
#include <cuda_fp16.h>
#include <cstdint>

#define N_NODES 50000
#define N_PAD   50048          // 391 * 128
#define R_REL   16
#define B_BASES 8
#define DIN     128
#define DOUT    128
#define NNZ     1600000
#define M_TILES 391

typedef unsigned int uint;

// Scratch: device globals (no allocation allowed)
__device__ __nv_bfloat16 g_Xh[(size_t)N_PAD * DIN];
__device__ __nv_bfloat16 g_Xl[(size_t)N_PAD * DIN];
__device__ __nv_bfloat16 g_BTh[B_BASES * DOUT * DIN];
__device__ __nv_bfloat16 g_BTl[B_BASES * DOUT * DIN];
__device__ float  g_XB[(size_t)B_BASES * N_NODES * DOUT];   // 204.8 MB
__device__ __half g_FW[(size_t)R_REL * N_NODES * DOUT];     // 204.8 MB (fp16)
__device__ int    g_idx64;
// CSR binning scratch
__device__ int   g_cnt[N_NODES];
__device__ int   g_start[N_NODES + 1];
__device__ int   g_cursor[N_NODES];
__device__ int2  g_edge[NNZ];

// ---------------------------------------------------------------------------
__device__ __forceinline__ uint32_t smem_u32(const void* p) {
    uint32_t a;
    asm("{ .reg .u64 t; cvta.to.shared.u64 t, %1; cvt.u32.u64 %0, t; }"
        : "=r"(a) : "l"(p));
    return a;
}
__device__ __forceinline__ void ldsm_x4(uint r[4], uint32_t addr) {
    asm volatile("ldmatrix.sync.aligned.m8n8.x4.shared.b16 {%0,%1,%2,%3}, [%4];"
                 : "=r"(r[0]), "=r"(r[1]), "=r"(r[2]), "=r"(r[3]) : "r"(addr));
}
__device__ __forceinline__ void mma_bf16(float c[4], const uint a[4], const uint b0, const uint b1) {
    asm volatile("mma.sync.aligned.m16n8k16.row.col.f32.bf16.bf16.f32 "
                 "{%0,%1,%2,%3},{%4,%5,%6,%7},{%8,%9},{%0,%1,%2,%3};"
                 : "+f"(c[0]), "+f"(c[1]), "+f"(c[2]), "+f"(c[3])
                 : "r"(a[0]), "r"(a[1]), "r"(a[2]), "r"(a[3]), "r"(b0), "r"(b1));
}
__device__ __forceinline__ void cp_async16(uint32_t dst, const void* src) {
    asm volatile("cp.async.cg.shared.global [%0], [%1], 16;" :: "r"(dst), "l"(src));
}
#define CP_COMMIT() asm volatile("cp.async.commit_group;" ::: "memory")
#define CP_WAIT(n)  asm volatile("cp.async.wait_group %0;" :: "n"(n) : "memory")

// ---------------------------------------------------------------------------
__global__ void detect_dtype_kernel(const unsigned int* __restrict__ rows_raw) {
    bool all_hi_zero = true;
    for (int i = 0; i < 64; i++)
        if (rows_raw[2 * i + 1] != 0u) { all_hi_zero = false; break; }
    g_idx64 = all_hi_zero ? 1 : 0;
}

__global__ void zero_cnt_kernel() {
    int i = blockIdx.x * blockDim.x + threadIdx.x;
    if (i < N_NODES) g_cnt[i] = 0;
}

__global__ void hist_kernel(const void* __restrict__ rows) {
    const int e = blockIdx.x * blockDim.x + threadIdx.x;
    if (e >= NNZ) return;
    int row = g_idx64 ? (int)((const unsigned int*)rows)[2 * e]
                      : ((const int*)rows)[e];
    atomicAdd(&g_cnt[row], 1);
}

__global__ void __launch_bounds__(1024, 1) scan_kernel() {
    __shared__ int wsum[32];
    __shared__ int carry;
    const int tid = threadIdx.x, lane = tid & 31, wid = tid >> 5;
    if (tid == 0) carry = 0;
    __syncthreads();
    for (int base = 0; base < N_NODES; base += 1024) {
        const int i = base + tid;
        int v = (i < N_NODES) ? g_cnt[i] : 0;
        int x = v;
#pragma unroll
        for (int off = 1; off < 32; off <<= 1) {
            int y = __shfl_up_sync(0xffffffffu, x, off);
            if (lane >= off) x += y;
        }
        if (lane == 31) wsum[wid] = x;
        __syncthreads();
        if (wid == 0) {
            int s = wsum[lane];
#pragma unroll
            for (int off = 1; off < 32; off <<= 1) {
                int y = __shfl_up_sync(0xffffffffu, s, off);
                if (lane >= off) s += y;
            }
            wsum[lane] = s;
        }
        __syncthreads();
        const int warpOff = (wid == 0) ? 0 : wsum[wid - 1];
        const int excl = carry + warpOff + x - v;
        if (i < N_NODES) { g_start[i] = excl; g_cursor[i] = excl; }
        __syncthreads();
        if (tid == 0) carry += wsum[31];
        __syncthreads();
    }
    if (tid == 0) g_start[N_NODES] = carry;
}

__global__ void fill_kernel(const void* __restrict__ rows,
                            const void* __restrict__ cols,
                            const float* __restrict__ vals) {
    const int e = blockIdx.x * blockDim.x + threadIdx.x;
    if (e >= NNZ) return;
    int row, col;
    if (g_idx64) {
        row = (int)((const unsigned int*)rows)[2 * e];
        col = (int)((const unsigned int*)cols)[2 * e];
    } else {
        row = ((const int*)rows)[e];
        col = ((const int*)cols)[e];
    }
    const int pos = atomicAdd(&g_cursor[row], 1);
    g_edge[pos] = make_int2(col, __float_as_int(vals[e]));
}

// ---------------------------------------------------------------------------
__global__ void prep_x_kernel(const float* __restrict__ X) {
    const int id = blockIdx.x * blockDim.x + threadIdx.x;
    if (id >= (N_PAD * DIN) / 8) return;
    const size_t base = (size_t)id * 8;
    const int row = (int)(base >> 7);
    __nv_bfloat16 h[8], l[8];
    if (row < N_NODES) {
        float v[8];
        *(float4*)&v[0] = *(const float4*)(X + base);
        *(float4*)&v[4] = *(const float4*)(X + base + 4);
#pragma unroll
        for (int i = 0; i < 8; i++) {
            h[i] = __float2bfloat16_rn(v[i]);
            l[i] = __float2bfloat16_rn(v[i] - __bfloat162float(h[i]));
        }
    } else {
#pragma unroll
        for (int i = 0; i < 8; i++) { h[i] = __float2bfloat16_rn(0.f); l[i] = h[i]; }
    }
    *(uint4*)(g_Xh + base) = *(uint4*)h;
    *(uint4*)(g_Xl + base) = *(uint4*)l;
}

__global__ void prep_bt_kernel(const float* __restrict__ basis) {
    const int id = blockIdx.x * blockDim.x + threadIdx.x;
    if (id >= B_BASES * DOUT * (DIN / 4)) return;
    const int k4 = (id & 31) * 4;
    const int n  = (id >> 5) & 127;
    const int b  = id >> 12;
    __nv_bfloat16 h[4], l[4];
#pragma unroll
    for (int i = 0; i < 4; i++) {
        float v = basis[(size_t)b * DIN * DOUT + (size_t)(k4 + i) * DOUT + n];
        h[i] = __float2bfloat16_rn(v);
        l[i] = __float2bfloat16_rn(v - __bfloat162float(h[i]));
    }
    const size_t off = (size_t)b * DOUT * DIN + (size_t)n * DIN + k4;
    *(uint2*)(g_BTh + off) = *(uint2*)h;
    *(uint2*)(g_BTl + off) = *(uint2*)l;
}

// ---------------------------------------------------------------------------
// XB[b] = X @ basis[b] via mma.sync bf16 split-3, cp.async double-buffered.
// grid (391, 8), 256 threads, 2 CTAs/SM (96 KB smem).  (unchanged from R8)
// ---------------------------------------------------------------------------
#define S_BH   0
#define S_BL   32768
#define S_X    65536
#define XBUF   16384
#define S_TOTAL 98304

__global__ void __launch_bounds__(256, 2)
gemm_mma_kernel(int dummy) {
    extern __shared__ __align__(1024) unsigned char smem[];
    const uint32_t sbase = smem_u32(smem);
    const int tid  = threadIdx.x;
    const int wid  = tid >> 5;
    const int lane = tid & 31;
    const int b    = blockIdx.y;
    const int m0   = blockIdx.x * 128;

    const int wm = wid >> 1;
    const int wn = wid & 1;

    {
        const size_t bBase = (size_t)b * DOUT * DIN;
#pragma unroll
        for (int i = 0; i < 8; i++) {
            const int slot = i * 256 + tid;
            const int row  = slot >> 4;
            const int c    = slot & 15;
            const uint32_t dst = (uint32_t)(row * 256 + ((c ^ (row & 7)) << 4));
            const size_t src = bBase + (size_t)row * DIN + c * 8;
            cp_async16(sbase + S_BH + dst, g_BTh + src);
            cp_async16(sbase + S_BL + dst, g_BTl + src);
        }
    }
    CP_COMMIT();
#pragma unroll
    for (int i = 0; i < 2; i++) {
        const int slot = i * 256 + tid;
        const int row  = slot >> 2;
        const int c    = slot & 3;
        const uint32_t dst = (uint32_t)(row * 64 + ((c ^ ((row >> 1) & 3)) << 4));
        const size_t src = (size_t)(m0 + row) * DIN + c * 8;
        cp_async16(sbase + S_X + dst, g_Xh + src);
        cp_async16(sbase + S_X + 8192 + dst, g_Xl + src);
    }
    CP_COMMIT();

    float acc[2][8][4];
#pragma unroll
    for (int mf = 0; mf < 2; mf++)
#pragma unroll
        for (int nf = 0; nf < 8; nf++)
#pragma unroll
            for (int q = 0; q < 4; q++) acc[mf][nf][q] = 0.f;

    const int a_row0 = wm * 32 + (lane & 15);
    const int a_ch   = lane >> 4;
    const int b_row0 = wn * 64 + (lane & 7) + ((lane >> 4) << 3);
    const int b_ch   = (lane >> 3) & 1;

#pragma unroll
    for (int kc = 0; kc < 4; kc++) {
        if (kc < 3) {
            const uint32_t xb = sbase + S_X + ((kc + 1) & 1) * XBUF;
#pragma unroll
            for (int i = 0; i < 2; i++) {
                const int slot = i * 256 + tid;
                const int row  = slot >> 2;
                const int c    = slot & 3;
                const uint32_t dst = (uint32_t)(row * 64 + ((c ^ ((row >> 1) & 3)) << 4));
                const size_t src = (size_t)(m0 + row) * DIN + (kc + 1) * 32 + c * 8;
                cp_async16(xb + dst, g_Xh + src);
                cp_async16(xb + 8192 + dst, g_Xl + src);
            }
            CP_COMMIT();
            CP_WAIT(1);
        } else {
            CP_WAIT(0);
        }
        __syncthreads();

        const uint32_t xh = sbase + S_X + (kc & 1) * XBUF;
        const uint32_t xl = xh + 8192;

#pragma unroll
        for (int kfi = 0; kfi < 2; kfi++) {
            const int kf = kc * 2 + kfi;
            uint Ah[2][4], Al[2][4];
#pragma unroll
            for (int mf = 0; mf < 2; mf++) {
                const int row = a_row0 + mf * 16;
                const uint32_t addr = (uint32_t)(row * 64 +
                    (((kfi * 2 + a_ch) ^ ((row >> 1) & 3)) << 4));
                ldsm_x4(Ah[mf], xh + addr);
                ldsm_x4(Al[mf], xl + addr);
            }
#pragma unroll
            for (int p = 0; p < 4; p++) {
                const int row = b_row0 + p * 16;
                const uint32_t addr = (uint32_t)(row * 256 +
                    (((kf * 2 + b_ch) ^ (row & 7)) << 4));
                uint Bh[4];
                ldsm_x4(Bh, sbase + S_BH + addr);
#pragma unroll
                for (int mf = 0; mf < 2; mf++) {
                    mma_bf16(acc[mf][2 * p],     Ah[mf], Bh[0], Bh[1]);
                    mma_bf16(acc[mf][2 * p + 1], Ah[mf], Bh[2], Bh[3]);
                    mma_bf16(acc[mf][2 * p],     Al[mf], Bh[0], Bh[1]);
                    mma_bf16(acc[mf][2 * p + 1], Al[mf], Bh[2], Bh[3]);
                }
                uint Bl[4];
                ldsm_x4(Bl, sbase + S_BL + addr);
#pragma unroll
                for (int mf = 0; mf < 2; mf++) {
                    mma_bf16(acc[mf][2 * p],     Ah[mf], Bl[0], Bl[1]);
                    mma_bf16(acc[mf][2 * p + 1], Ah[mf], Bl[2], Bl[3]);
                }
            }
        }
        __syncthreads();
    }

    float* outBase = g_XB + (size_t)b * N_NODES * DOUT;
    const int g = lane >> 2;
    const int t2 = (lane & 3) * 2;
#pragma unroll
    for (int mf = 0; mf < 2; mf++) {
        const int r0 = m0 + wm * 32 + mf * 16 + g;
#pragma unroll
        for (int nf = 0; nf < 8; nf++) {
            const int col = wn * 64 + nf * 8 + t2;
            if (r0 < N_NODES)
                *(float2*)(outBase + (size_t)r0 * DOUT + col) =
                    make_float2(acc[mf][nf][0], acc[mf][nf][1]);
            if (r0 + 8 < N_NODES)
                *(float2*)(outBase + (size_t)(r0 + 8) * DOUT + col) =
                    make_float2(acc[mf][nf][2], acc[mf][nf][3]);
        }
    }
}

// ---------------------------------------------------------------------------
// FW[r][n][d] = sum_b comp[r][b] * XB[b][n][d]   (fp32 math, fp16 store)
// ---------------------------------------------------------------------------
__global__ __launch_bounds__(256)
void combine_kernel(const float* __restrict__ comp) {
    __shared__ float cs[R_REL * B_BASES];
    if (threadIdx.x < R_REL * B_BASES) cs[threadIdx.x] = comp[threadIdx.x];
    __syncthreads();

    const int id = blockIdx.x * blockDim.x + threadIdx.x;
    if (id >= N_NODES * 32) return;
    const int n  = id >> 5;
    const int d4 = (id & 31) * 4;

    float4 xb[8];
#pragma unroll
    for (int b = 0; b < B_BASES; b++)
        xb[b] = __ldg((const float4*)(g_XB + ((size_t)b * N_NODES + n) * DOUT + d4));

#pragma unroll
    for (int r = 0; r < R_REL; r++) {
        float4 o = make_float4(0.f, 0.f, 0.f, 0.f);
#pragma unroll
        for (int b = 0; b < B_BASES; b++) {
            const float c = cs[r * B_BASES + b];
            o.x += c * xb[b].x;
            o.y += c * xb[b].y;
            o.z += c * xb[b].z;
            o.w += c * xb[b].w;
        }
        __half2 h0 = __floats2half2_rn(o.x, o.y);
        __half2 h1 = __floats2half2_rn(o.z, o.w);
        uint2 pk;
        pk.x = *(uint32_t*)&h0;
        pk.y = *(uint32_t*)&h1;
        *(uint2*)(g_FW + ((size_t)r * N_NODES + n) * DOUT + d4) = pk;
    }
}

// ---------------------------------------------------------------------------
// Sorted scatter: one warp per output row; fp16 FW gather (8 B/lane/edge),
// fp32 accumulation, single non-atomic fp32 row write.
// ---------------------------------------------------------------------------
__device__ __forceinline__ float4 fw_row_f4(int col, int lane) {
    const uint2 pk = __ldg((const uint2*)(g_FW + (size_t)col * DOUT) + lane);
    const float2 a = __half22float2(*(const __half2*)&pk.x);
    const float2 b = __half22float2(*(const __half2*)&pk.y);
    return make_float4(a.x, a.y, b.x, b.y);
}

__global__ void __launch_bounds__(256)
scatter2_kernel(float* __restrict__ out) {
    const int warpId = (blockIdx.x * blockDim.x + threadIdx.x) >> 5;
    if (warpId >= N_NODES) return;
    const int lane = threadIdx.x & 31;

    const int s = g_start[warpId];
    const int e = g_start[warpId + 1];

    float4 acc = make_float4(0.f, 0.f, 0.f, 0.f);
    int i = s;
    for (; i + 4 <= e; i += 4) {
        int2 e0 = g_edge[i], e1 = g_edge[i + 1], e2 = g_edge[i + 2], e3 = g_edge[i + 3];
        float4 f0 = fw_row_f4(e0.x, lane);
        float4 f1 = fw_row_f4(e1.x, lane);
        float4 f2 = fw_row_f4(e2.x, lane);
        float4 f3 = fw_row_f4(e3.x, lane);
        const float v0 = __int_as_float(e0.y), v1 = __int_as_float(e1.y);
        const float v2 = __int_as_float(e2.y), v3 = __int_as_float(e3.y);
        acc.x += v0 * f0.x + v1 * f1.x + v2 * f2.x + v3 * f3.x;
        acc.y += v0 * f0.y + v1 * f1.y + v2 * f2.y + v3 * f3.y;
        acc.z += v0 * f0.z + v1 * f1.z + v2 * f2.z + v3 * f3.z;
        acc.w += v0 * f0.w + v1 * f1.w + v2 * f2.w + v3 * f3.w;
    }
    for (; i < e; i++) {
        int2 ed = g_edge[i];
        float4 f = fw_row_f4(ed.x, lane);
        const float v = __int_as_float(ed.y);
        acc.x += v * f.x; acc.y += v * f.y; acc.z += v * f.z; acc.w += v * f.w;
    }
    *(float4*)(out + (size_t)warpId * DOUT + lane * 4) = acc;
}

// ---------------------------------------------------------------------------
extern "C" void kernel_launch(void* const* d_in, const int* in_sizes, int n_in,
                              void* d_out, int out_size) {
    const float* X      = (const float*)d_in[0];
    const void*  A_rows = d_in[1];
    const void*  A_cols = d_in[2];
    const float* A_vals = (const float*)d_in[3];
    const float* basis  = (const float*)d_in[4];
    const float* comp   = (const float*)d_in[5];
    float* out = (float*)d_out;

    cudaFuncSetAttribute(gemm_mma_kernel,
                         cudaFuncAttributeMaxDynamicSharedMemorySize, S_TOTAL);

    // gemm_mma_kernel stays launch #4 so ncu (-s 5 -c 1) profiles it.
    detect_dtype_kernel<<<1, 1>>>((const unsigned int*)A_rows);         // 1

    const int px = (N_PAD * DIN) / 8;
    prep_x_kernel<<<(px + 255) / 256, 256>>>(X);                        // 2
    const int pb = B_BASES * DOUT * (DIN / 4);
    prep_bt_kernel<<<(pb + 255) / 256, 256>>>(basis);                   // 3

    dim3 ggrid(M_TILES, B_BASES);
    gemm_mma_kernel<<<ggrid, 256, S_TOTAL>>>(0);                        // 4 (profiled)

    zero_cnt_kernel<<<(N_NODES + 255) / 256, 256>>>();                  // 5
    hist_kernel<<<(NNZ + 255) / 256, 256>>>(A_rows);                    // 6
    scan_kernel<<<1, 1024>>>();                                         // 7
    fill_kernel<<<(NNZ + 255) / 256, 256>>>(A_rows, A_cols, A_vals);    // 8

    const int cthreads = N_NODES * 32;
    combine_kernel<<<(cthreads + 255) / 256, 256>>>(comp);              // 9

    const long long sthreads = (long long)N_NODES * 32;
    scatter2_kernel<<<(unsigned)((sthreads + 255) / 256), 256>>>(out);  // 10
}

// round 10
// speedup vs baseline: 1.5586x; 1.0384x over previous
#include <cuda_runtime.h>
#include <cuda_bf16.h>
#include <cuda_fp16.h>
#include <cstdint>

#define N_NODES 50000
#define N_PAD   50048          // 391 * 128
#define R_REL   16
#define B_BASES 8
#define DIN     128
#define DOUT    128
#define NNZ     1600000
#define M_TILES 391

typedef unsigned int uint;

// Scratch: device globals (no allocation allowed)
__device__ __nv_bfloat16 g_Xh[(size_t)N_PAD * DIN];
__device__ __nv_bfloat16 g_Xl[(size_t)N_PAD * DIN];
__device__ __nv_bfloat16 g_BTh[B_BASES * DOUT * DIN];
__device__ __nv_bfloat16 g_BTl[B_BASES * DOUT * DIN];
__device__ __half g_XB[(size_t)B_BASES * N_NODES * DOUT];   // 102.4 MB (fp16)
__device__ __half g_FW[(size_t)R_REL * N_NODES * DOUT];     // 204.8 MB (fp16)
__device__ int    g_idx64;
// CSR binning scratch
__device__ int   g_cnt[N_NODES];
__device__ int   g_start[N_NODES + 1];
__device__ int   g_cursor[N_NODES];
__device__ int2  g_edge[NNZ];

// ---------------------------------------------------------------------------
__device__ __forceinline__ uint32_t smem_u32(const void* p) {
    uint32_t a;
    asm("{ .reg .u64 t; cvta.to.shared.u64 t, %1; cvt.u32.u64 %0, t; }"
        : "=r"(a) : "l"(p));
    return a;
}
__device__ __forceinline__ void ldsm_x4(uint r[4], uint32_t addr) {
    asm volatile("ldmatrix.sync.aligned.m8n8.x4.shared.b16 {%0,%1,%2,%3}, [%4];"
                 : "=r"(r[0]), "=r"(r[1]), "=r"(r[2]), "=r"(r[3]) : "r"(addr));
}
__device__ __forceinline__ void mma_bf16(float c[4], const uint a[4], const uint b0, const uint b1) {
    asm volatile("mma.sync.aligned.m16n8k16.row.col.f32.bf16.bf16.f32 "
                 "{%0,%1,%2,%3},{%4,%5,%6,%7},{%8,%9},{%0,%1,%2,%3};"
                 : "+f"(c[0]), "+f"(c[1]), "+f"(c[2]), "+f"(c[3])
                 : "r"(a[0]), "r"(a[1]), "r"(a[2]), "r"(a[3]), "r"(b0), "r"(b1));
}
__device__ __forceinline__ void cp_async16(uint32_t dst, const void* src) {
    asm volatile("cp.async.cg.shared.global [%0], [%1], 16;" :: "r"(dst), "l"(src));
}
#define CP_COMMIT() asm volatile("cp.async.commit_group;" ::: "memory")
#define CP_WAIT(n)  asm volatile("cp.async.wait_group %0;" :: "n"(n) : "memory")

// ---------------------------------------------------------------------------
__global__ void detect_dtype_kernel(const unsigned int* __restrict__ rows_raw) {
    bool all_hi_zero = true;
    for (int i = 0; i < 64; i++)
        if (rows_raw[2 * i + 1] != 0u) { all_hi_zero = false; break; }
    g_idx64 = all_hi_zero ? 1 : 0;
}

__global__ void zero_cnt_kernel() {
    int i = blockIdx.x * blockDim.x + threadIdx.x;
    if (i < N_NODES) g_cnt[i] = 0;
}

__global__ void hist_kernel(const void* __restrict__ rows) {
    const int e = blockIdx.x * blockDim.x + threadIdx.x;
    if (e >= NNZ) return;
    int row = g_idx64 ? (int)((const unsigned int*)rows)[2 * e]
                      : ((const int*)rows)[e];
    atomicAdd(&g_cnt[row], 1);
}

__global__ void __launch_bounds__(1024, 1) scan_kernel() {
    __shared__ int wsum[32];
    __shared__ int carry;
    const int tid = threadIdx.x, lane = tid & 31, wid = tid >> 5;
    if (tid == 0) carry = 0;
    __syncthreads();
    for (int base = 0; base < N_NODES; base += 1024) {
        const int i = base + tid;
        int v = (i < N_NODES) ? g_cnt[i] : 0;
        int x = v;
#pragma unroll
        for (int off = 1; off < 32; off <<= 1) {
            int y = __shfl_up_sync(0xffffffffu, x, off);
            if (lane >= off) x += y;
        }
        if (lane == 31) wsum[wid] = x;
        __syncthreads();
        if (wid == 0) {
            int s = wsum[lane];
#pragma unroll
            for (int off = 1; off < 32; off <<= 1) {
                int y = __shfl_up_sync(0xffffffffu, s, off);
                if (lane >= off) s += y;
            }
            wsum[lane] = s;
        }
        __syncthreads();
        const int warpOff = (wid == 0) ? 0 : wsum[wid - 1];
        const int excl = carry + warpOff + x - v;
        if (i < N_NODES) { g_start[i] = excl; g_cursor[i] = excl; }
        __syncthreads();
        if (tid == 0) carry += wsum[31];
        __syncthreads();
    }
    if (tid == 0) g_start[N_NODES] = carry;
}

__global__ void fill_kernel(const void* __restrict__ rows,
                            const void* __restrict__ cols,
                            const float* __restrict__ vals) {
    const int e = blockIdx.x * blockDim.x + threadIdx.x;
    if (e >= NNZ) return;
    int row, col;
    if (g_idx64) {
        row = (int)((const unsigned int*)rows)[2 * e];
        col = (int)((const unsigned int*)cols)[2 * e];
    } else {
        row = ((const int*)rows)[e];
        col = ((const int*)cols)[e];
    }
    const int pos = atomicAdd(&g_cursor[row], 1);
    g_edge[pos] = make_int2(col, __float_as_int(vals[e]));
}

// ---------------------------------------------------------------------------
__global__ void prep_x_kernel(const float* __restrict__ X) {
    const int id = blockIdx.x * blockDim.x + threadIdx.x;
    if (id >= (N_PAD * DIN) / 8) return;
    const size_t base = (size_t)id * 8;
    const int row = (int)(base >> 7);
    __nv_bfloat16 h[8], l[8];
    if (row < N_NODES) {
        float v[8];
        *(float4*)&v[0] = *(const float4*)(X + base);
        *(float4*)&v[4] = *(const float4*)(X + base + 4);
#pragma unroll
        for (int i = 0; i < 8; i++) {
            h[i] = __float2bfloat16_rn(v[i]);
            l[i] = __float2bfloat16_rn(v[i] - __bfloat162float(h[i]));
        }
    } else {
#pragma unroll
        for (int i = 0; i < 8; i++) { h[i] = __float2bfloat16_rn(0.f); l[i] = h[i]; }
    }
    *(uint4*)(g_Xh + base) = *(uint4*)h;
    *(uint4*)(g_Xl + base) = *(uint4*)l;
}

__global__ void prep_bt_kernel(const float* __restrict__ basis) {
    const int id = blockIdx.x * blockDim.x + threadIdx.x;
    if (id >= B_BASES * DOUT * (DIN / 4)) return;
    const int k4 = (id & 31) * 4;
    const int n  = (id >> 5) & 127;
    const int b  = id >> 12;
    __nv_bfloat16 h[4], l[4];
#pragma unroll
    for (int i = 0; i < 4; i++) {
        float v = basis[(size_t)b * DIN * DOUT + (size_t)(k4 + i) * DOUT + n];
        h[i] = __float2bfloat16_rn(v);
        l[i] = __float2bfloat16_rn(v - __bfloat162float(h[i]));
    }
    const size_t off = (size_t)b * DOUT * DIN + (size_t)n * DIN + k4;
    *(uint2*)(g_BTh + off) = *(uint2*)h;
    *(uint2*)(g_BTl + off) = *(uint2*)l;
}

// ---------------------------------------------------------------------------
// XB[b] = X @ basis[b] via mma.sync bf16 split-3, cp.async double-buffered.
// grid (391, 8), 256 threads, 2 CTAs/SM (96 KB smem). Epilogue stores fp16.
// ---------------------------------------------------------------------------
#define S_BH   0
#define S_BL   32768
#define S_X    65536
#define XBUF   16384
#define S_TOTAL 98304

__global__ void __launch_bounds__(256, 2)
gemm_mma_kernel(int dummy) {
    extern __shared__ __align__(1024) unsigned char smem[];
    const uint32_t sbase = smem_u32(smem);
    const int tid  = threadIdx.x;
    const int wid  = tid >> 5;
    const int lane = tid & 31;
    const int b    = blockIdx.y;
    const int m0   = blockIdx.x * 128;

    const int wm = wid >> 1;
    const int wn = wid & 1;

    {
        const size_t bBase = (size_t)b * DOUT * DIN;
#pragma unroll
        for (int i = 0; i < 8; i++) {
            const int slot = i * 256 + tid;
            const int row  = slot >> 4;
            const int c    = slot & 15;
            const uint32_t dst = (uint32_t)(row * 256 + ((c ^ (row & 7)) << 4));
            const size_t src = bBase + (size_t)row * DIN + c * 8;
            cp_async16(sbase + S_BH + dst, g_BTh + src);
            cp_async16(sbase + S_BL + dst, g_BTl + src);
        }
    }
    CP_COMMIT();
#pragma unroll
    for (int i = 0; i < 2; i++) {
        const int slot = i * 256 + tid;
        const int row  = slot >> 2;
        const int c    = slot & 3;
        const uint32_t dst = (uint32_t)(row * 64 + ((c ^ ((row >> 1) & 3)) << 4));
        const size_t src = (size_t)(m0 + row) * DIN + c * 8;
        cp_async16(sbase + S_X + dst, g_Xh + src);
        cp_async16(sbase + S_X + 8192 + dst, g_Xl + src);
    }
    CP_COMMIT();

    float acc[2][8][4];
#pragma unroll
    for (int mf = 0; mf < 2; mf++)
#pragma unroll
        for (int nf = 0; nf < 8; nf++)
#pragma unroll
            for (int q = 0; q < 4; q++) acc[mf][nf][q] = 0.f;

    const int a_row0 = wm * 32 + (lane & 15);
    const int a_ch   = lane >> 4;
    const int b_row0 = wn * 64 + (lane & 7) + ((lane >> 4) << 3);
    const int b_ch   = (lane >> 3) & 1;

#pragma unroll
    for (int kc = 0; kc < 4; kc++) {
        if (kc < 3) {
            const uint32_t xb = sbase + S_X + ((kc + 1) & 1) * XBUF;
#pragma unroll
            for (int i = 0; i < 2; i++) {
                const int slot = i * 256 + tid;
                const int row  = slot >> 2;
                const int c    = slot & 3;
                const uint32_t dst = (uint32_t)(row * 64 + ((c ^ ((row >> 1) & 3)) << 4));
                const size_t src = (size_t)(m0 + row) * DIN + (kc + 1) * 32 + c * 8;
                cp_async16(xb + dst, g_Xh + src);
                cp_async16(xb + 8192 + dst, g_Xl + src);
            }
            CP_COMMIT();
            CP_WAIT(1);
        } else {
            CP_WAIT(0);
        }
        __syncthreads();

        const uint32_t xh = sbase + S_X + (kc & 1) * XBUF;
        const uint32_t xl = xh + 8192;

#pragma unroll
        for (int kfi = 0; kfi < 2; kfi++) {
            const int kf = kc * 2 + kfi;
            uint Ah[2][4], Al[2][4];
#pragma unroll
            for (int mf = 0; mf < 2; mf++) {
                const int row = a_row0 + mf * 16;
                const uint32_t addr = (uint32_t)(row * 64 +
                    (((kfi * 2 + a_ch) ^ ((row >> 1) & 3)) << 4));
                ldsm_x4(Ah[mf], xh + addr);
                ldsm_x4(Al[mf], xl + addr);
            }
#pragma unroll
            for (int p = 0; p < 4; p++) {
                const int row = b_row0 + p * 16;
                const uint32_t addr = (uint32_t)(row * 256 +
                    (((kf * 2 + b_ch) ^ (row & 7)) << 4));
                uint Bh[4];
                ldsm_x4(Bh, sbase + S_BH + addr);
#pragma unroll
                for (int mf = 0; mf < 2; mf++) {
                    mma_bf16(acc[mf][2 * p],     Ah[mf], Bh[0], Bh[1]);
                    mma_bf16(acc[mf][2 * p + 1], Ah[mf], Bh[2], Bh[3]);
                    mma_bf16(acc[mf][2 * p],     Al[mf], Bh[0], Bh[1]);
                    mma_bf16(acc[mf][2 * p + 1], Al[mf], Bh[2], Bh[3]);
                }
                uint Bl[4];
                ldsm_x4(Bl, sbase + S_BL + addr);
#pragma unroll
                for (int mf = 0; mf < 2; mf++) {
                    mma_bf16(acc[mf][2 * p],     Ah[mf], Bl[0], Bl[1]);
                    mma_bf16(acc[mf][2 * p + 1], Ah[mf], Bl[2], Bl[3]);
                }
            }
        }
        __syncthreads();
    }

    // --- epilogue: write XB[b] fp16 ---
    __half* outBase = g_XB + (size_t)b * N_NODES * DOUT;
    const int g = lane >> 2;
    const int t2 = (lane & 3) * 2;
#pragma unroll
    for (int mf = 0; mf < 2; mf++) {
        const int r0 = m0 + wm * 32 + mf * 16 + g;
#pragma unroll
        for (int nf = 0; nf < 8; nf++) {
            const int col = wn * 64 + nf * 8 + t2;
            if (r0 < N_NODES) {
                __half2 h = __floats2half2_rn(acc[mf][nf][0], acc[mf][nf][1]);
                *(uint32_t*)(outBase + (size_t)r0 * DOUT + col) = *(uint32_t*)&h;
            }
            if (r0 + 8 < N_NODES) {
                __half2 h = __floats2half2_rn(acc[mf][nf][2], acc[mf][nf][3]);
                *(uint32_t*)(outBase + (size_t)(r0 + 8) * DOUT + col) = *(uint32_t*)&h;
            }
        }
    }
}

// ---------------------------------------------------------------------------
// FW[r][n][d] = sum_b comp[r][b] * XB[b][n][d]   (fp16 in, fp32 math, fp16 out)
// ---------------------------------------------------------------------------
__global__ __launch_bounds__(256)
void combine_kernel(const float* __restrict__ comp) {
    __shared__ float cs[R_REL * B_BASES];
    if (threadIdx.x < R_REL * B_BASES) cs[threadIdx.x] = comp[threadIdx.x];
    __syncthreads();

    const int id = blockIdx.x * blockDim.x + threadIdx.x;
    if (id >= N_NODES * 32) return;
    const int n  = id >> 5;
    const int d4 = (id & 31) * 4;

    float4 xb[8];
#pragma unroll
    for (int b = 0; b < B_BASES; b++) {
        const uint2 pk = __ldg((const uint2*)(g_XB + ((size_t)b * N_NODES + n) * DOUT + d4));
        const float2 a = __half22float2(*(const __half2*)&pk.x);
        const float2 c = __half22float2(*(const __half2*)&pk.y);
        xb[b] = make_float4(a.x, a.y, c.x, c.y);
    }

#pragma unroll
    for (int r = 0; r < R_REL; r++) {
        float4 o = make_float4(0.f, 0.f, 0.f, 0.f);
#pragma unroll
        for (int b = 0; b < B_BASES; b++) {
            const float c = cs[r * B_BASES + b];
            o.x += c * xb[b].x;
            o.y += c * xb[b].y;
            o.z += c * xb[b].z;
            o.w += c * xb[b].w;
        }
        __half2 h0 = __floats2half2_rn(o.x, o.y);
        __half2 h1 = __floats2half2_rn(o.z, o.w);
        uint2 pk;
        pk.x = *(uint32_t*)&h0;
        pk.y = *(uint32_t*)&h1;
        *(uint2*)(g_FW + ((size_t)r * N_NODES + n) * DOUT + d4) = pk;
    }
}

// ---------------------------------------------------------------------------
// Sorted scatter: one warp per output row; fp16 FW gather (8 B/lane/edge),
// fp32 accumulation, single non-atomic fp32 row write.
// ---------------------------------------------------------------------------
__device__ __forceinline__ float4 fw_row_f4(int col, int lane) {
    const uint2 pk = __ldg((const uint2*)(g_FW + (size_t)col * DOUT) + lane);
    const float2 a = __half22float2(*(const __half2*)&pk.x);
    const float2 b = __half22float2(*(const __half2*)&pk.y);
    return make_float4(a.x, a.y, b.x, b.y);
}

__global__ void __launch_bounds__(256)
scatter2_kernel(float* __restrict__ out) {
    const int warpId = (blockIdx.x * blockDim.x + threadIdx.x) >> 5;
    if (warpId >= N_NODES) return;
    const int lane = threadIdx.x & 31;

    const int s = g_start[warpId];
    const int e = g_start[warpId + 1];

    float4 acc = make_float4(0.f, 0.f, 0.f, 0.f);
    int i = s;
    for (; i + 4 <= e; i += 4) {
        int2 e0 = g_edge[i], e1 = g_edge[i + 1], e2 = g_edge[i + 2], e3 = g_edge[i + 3];
        float4 f0 = fw_row_f4(e0.x, lane);
        float4 f1 = fw_row_f4(e1.x, lane);
        float4 f2 = fw_row_f4(e2.x, lane);
        float4 f3 = fw_row_f4(e3.x, lane);
        const float v0 = __int_as_float(e0.y), v1 = __int_as_float(e1.y);
        const float v2 = __int_as_float(e2.y), v3 = __int_as_float(e3.y);
        acc.x += v0 * f0.x + v1 * f1.x + v2 * f2.x + v3 * f3.x;
        acc.y += v0 * f0.y + v1 * f1.y + v2 * f2.y + v3 * f3.y;
        acc.z += v0 * f0.z + v1 * f1.z + v2 * f2.z + v3 * f3.z;
        acc.w += v0 * f0.w + v1 * f1.w + v2 * f2.w + v3 * f3.w;
    }
    for (; i < e; i++) {
        int2 ed = g_edge[i];
        float4 f = fw_row_f4(ed.x, lane);
        const float v = __int_as_float(ed.y);
        acc.x += v * f.x; acc.y += v * f.y; acc.z += v * f.z; acc.w += v * f.w;
    }
    *(float4*)(out + (size_t)warpId * DOUT + lane * 4) = acc;
}

// ---------------------------------------------------------------------------
extern "C" void kernel_launch(void* const* d_in, const int* in_sizes, int n_in,
                              void* d_out, int out_size) {
    const float* X      = (const float*)d_in[0];
    const void*  A_rows = d_in[1];
    const void*  A_cols = d_in[2];
    const float* A_vals = (const float*)d_in[3];
    const float* basis  = (const float*)d_in[4];
    const float* comp   = (const float*)d_in[5];
    float* out = (float*)d_out;

    cudaFuncSetAttribute(gemm_mma_kernel,
                         cudaFuncAttributeMaxDynamicSharedMemorySize, S_TOTAL);

    // gemm_mma_kernel stays launch #4 so ncu (-s 5 -c 1) profiles it.
    detect_dtype_kernel<<<1, 1>>>((const unsigned int*)A_rows);         // 1

    const int px = (N_PAD * DIN) / 8;
    prep_x_kernel<<<(px + 255) / 256, 256>>>(X);                        // 2
    const int pb = B_BASES * DOUT * (DIN / 4);
    prep_bt_kernel<<<(pb + 255) / 256, 256>>>(basis);                   // 3

    dim3 ggrid(M_TILES, B_BASES);
    gemm_mma_kernel<<<ggrid, 256, S_TOTAL>>>(0);                        // 4 (profiled)

    zero_cnt_kernel<<<(N_NODES + 255) / 256, 256>>>();                  // 5
    hist_kernel<<<(NNZ + 255) / 256, 256>>>(A_rows);                    // 6
    scan_kernel<<<1, 1024>>>();                                         // 7
    fill_kernel<<<(NNZ + 255) / 256, 256>>>(A_rows, A_cols, A_vals);    // 8

    const int cthreads = N_NODES * 32;
    combine_kernel<<<(cthreads + 255) / 256, 256>>>(comp);              // 9

    const long long sthreads = (long long)N_NODES * 32;
    scatter2_kernel<<<(unsigned)((sthreads + 255) / 256), 256>>>(out);  // 10
}